// round 15
// baseline (speedup 1.0000x reference)
#include <cuda_runtime.h>
#include <math.h>

// Problem dims
#define BB   2
#define CCH  16
#define HH   128
#define WW   128
#define MM   9
#define NDD  9
#define MCC  144
#define HIDN 18
#define OUTC 150
#define HW   (HH*WW)       // 16384
#define HWD  (HH*WW*NDD)   // 147456
#define EPSBN 1e-5f

// Scratch (device globals). Channel-pair interleaved layouts:
// g_cv2[b][cp][p][c] : cp=0..71, p=pix*9+d, c=channel parity (pairs adjacent)
__device__ float g_cv2[BB*(size_t)72*HWD*2];
__device__ float g_h12[BB*(size_t)9*HWD*2];   // hidden, 9 cpairs interleaved
__device__ float g_wei[BB*(size_t)MM*HWD];    // sigmoid attention (plain)
__device__ float g_p  [BB*MCC];               // global mean pool
__device__ float g_xg [BB*MM];                // global-branch logits
// conv weights: [g][cpair][grp=k0*3+k1][20]: floats 0..17 = (k2*3+o)*2+par, 18-19 pad
__device__ float g_w1p[6*72*180];
__device__ float g_w2p[3*9*180];

typedef unsigned long long u64;

__device__ __forceinline__ void upk2(float &lo, float &hi, u64 v) {
    unsigned a, b;
    asm("mov.b64 {%0, %1}, %2;" : "=r"(a), "=r"(b) : "l"(v));
    lo = __uint_as_float(a); hi = __uint_as_float(b);
}
__device__ __forceinline__ void fma2(u64 &d, u64 a, u64 b) {
    asm("fma.rn.f32x2 %0, %1, %2, %0;" : "+l"(d) : "l"(a), "l"(b));
}
__device__ __forceinline__ u64 pk2(float lo, float hi) {
    u64 r;
    asm("mov.b64 %0, {%1, %2};" : "=l"(r) : "r"(__float_as_uint(lo)), "r"(__float_as_uint(hi)));
    return r;
}
__device__ __forceinline__ void cpa8(unsigned saddr, const void* gaddr, bool valid) {
    int sz = valid ? 8 : 0;   // src-size 0 -> zero-fill
    asm volatile("cp.async.ca.shared.global [%0], [%1], 8, %2;"
                 :: "r"(saddr), "l"(gaddr), "r"(sz));
}
__device__ __forceinline__ void cpa_commit() {
    asm volatile("cp.async.commit_group;");
}

// ---------------------------------------------------------------------------
// K-pack: channel-pair interleave conv weights, 80B-aligned tap groups.
// ---------------------------------------------------------------------------
__global__ void k_packw(const float* __restrict__ w1, const float* __restrict__ w2) {
    int t = blockIdx.x * 256 + threadIdx.x;
    if (t < HIDN*MCC*27) {
        int tap = t % 27; int r = t / 27;
        int ch = r % MCC; int oc = r / MCC;
        int k0 = tap / 9, k1 = (tap / 3) % 3, k2 = tap % 3;
        int g = oc / 3, o = oc % 3;
        int cp = ch >> 1, par = ch & 1;
        float v = w1[((size_t)oc*MCC + ch)*27 + tap];
        g_w1p[(((size_t)(g*72 + cp)*9 + (k0*3 + k1))*20) + (k2*3 + o)*2 + par] = v;
    }
    if (t < MM*HIDN*27) {
        int tap = t % 27; int r = t / 27;
        int ch = r % HIDN; int oc = r / HIDN;
        int k0 = tap / 9, k1 = (tap / 3) % 3, k2 = tap % 3;
        int g = oc / 3, o = oc % 3;
        int cp = ch >> 1, par = ch & 1;
        float v = w2[((size_t)oc*HIDN + ch)*27 + tap];
        g_w2p[(((size_t)(g*9 + cp)*9 + (k0*3 + k1))*20) + (k2*3 + o)*2 + par] = v;
    }
}

// ---------------------------------------------------------------------------
// K1: build cost volume, channel-pair interleaved. One thread per (b,cp,pix).
// ---------------------------------------------------------------------------
__global__ void k_build_cv(const float* __restrict__ x) {
    unsigned idx = blockIdx.x * 256 + threadIdx.x;
    if (idx >= (unsigned)(BB*72*HW)) return;
    unsigned i = idx;
    int pix = i % HW;  i /= HW;
    int cp  = i % 72;
    int b   = i / 72;
    int mc0 = 2*cp;
    int m = mc0 / CCH, ch = mc0 % CCH;
    int w = pix & 127, h = pix >> 7;
    int s = m - 4;
    const float* x0 = x + ((size_t)(b*CCH + ch)*HW + h*WW)*MM + m;
    const float* x1 = x0 + (size_t)HW*MM;   // channel ch+1, same m
    float2* dst = ((float2*)g_cv2) + ((size_t)(b*72 + cp)*HWD + (size_t)pix*9);
#pragma unroll
    for (int d = 0; d < 9; d++) {
        int ws = w + (d - 4)*s;
        float2 v = make_float2(0.f, 0.f);
        if ((unsigned)ws < WW) {
            v.x = x0[(size_t)ws*MM];
            v.y = x1[(size_t)ws*MM];
        }
        dst[d] = v;
    }
}

// ---------------------------------------------------------------------------
// K2: mean pool per (b,mc) computed directly from x with shift multiplicity.
// ---------------------------------------------------------------------------
__global__ void k_reduce(const float* __restrict__ x) {
    int bm = blockIdx.x;                 // 0..287
    int b = bm / MCC, mc = bm % MCC;
    int m = mc / CCH, ch = mc % CCH;
    int s = m - 4;
    const float* xb = x + ((size_t)(b*CCH + ch)*HW)*MM + m;
    float sum = 0.f;
    for (int i = threadIdx.x; i < HW; i += 256) {
        int wp = i & 127;
        int cnt = 0;
#pragma unroll
        for (int d = 0; d < 9; d++) {
            int wsrc = wp - (d - 4)*s;
            cnt += ((unsigned)wsrc < WW) ? 1 : 0;
        }
        sum += xb[(size_t)i*MM] * (float)cnt;
    }
    __shared__ float sh[256];
    sh[threadIdx.x] = sum;
    __syncthreads();
    for (int o = 128; o > 0; o >>= 1) {
        if (threadIdx.x < o) sh[threadIdx.x] += sh[threadIdx.x + o];
        __syncthreads();
    }
    if (threadIdx.x == 0) g_p[bm] = sh[0] * (1.0f / HWD);
}

// ---------------------------------------------------------------------------
// K3: global attention branch (center tap only at 1x1x1 spatial).
// ---------------------------------------------------------------------------
__global__ void k_global(const float* __restrict__ w1, const float* __restrict__ b1,
                         const float* __restrict__ g1, const float* __restrict__ be1,
                         const float* __restrict__ m1, const float* __restrict__ v1,
                         const float* __restrict__ w2, const float* __restrict__ b2,
                         const float* __restrict__ g2, const float* __restrict__ be2,
                         const float* __restrict__ m2, const float* __restrict__ v2) {
    __shared__ float gh[BB*HIDN];
    int t = threadIdx.x;
    if (t < BB*HIDN) {
        int b = t / HIDN, o = t % HIDN;
        float s = b1[o];
        for (int c = 0; c < MCC; c++)
            s += w1[(o*MCC + c)*27 + 13] * g_p[b*MCC + c];
        float sc = g1[o] * rsqrtf(v1[o] + EPSBN);
        s = (s - m1[o]) * sc + be1[o];
        gh[t] = fmaxf(s, 0.f);
    }
    __syncthreads();
    if (t < BB*MM) {
        int b = t / MM, og = t % MM;
        float s = b2[og];
        for (int o = 0; o < HIDN; o++)
            s += w2[(og*HIDN + o)*27 + 13] * gh[b*HIDN + o];
        float sc = g2[og] * rsqrtf(v2[og] + EPSBN);
        g_xg[t] = (s - m2[og]) * sc + be2[og];
    }
}

// ---------------------------------------------------------------------------
// K4/K5: 3x3x3 conv, f32x2 channel-pair, cp.async.8 2-buffer pipeline with
// ONE barrier per step. Cell = 28 floats (112B, conflict-free).
// __launch_bounds__(128,5): 5 blocks/SM -> capacity 740 -> 2.08 waves for
// grid 1536 (was 2.59 @4 blocks). Register diet: no staging arrays; each
// LDS.128 feeds its FMA2s directly.
// Block 128 = 16(w) x 8(h). grid z = B*NOCG (3 oc per group).
// ---------------------------------------------------------------------------
template<int CPAIRS, int NOCG, bool FIRST>
__global__ __launch_bounds__(128, 5) void k_conv(
        const float* __restrict__ gam, const float* __restrict__ bet,
        const float* __restrict__ mu,  const float* __restrict__ var,
        const float* __restrict__ bias) {
    __shared__ __align__(16) float tile[2][180*28];
    __shared__ __align__(16) float wsh[2][180];

    const float* src = FIRST ? g_cv2 : g_h12;
    const float* wpk = FIRST ? g_w1p : g_w2p;

    int tid = threadIdx.x;
    int tx = tid & 15, ty = tid >> 4;        // 16 x 8
    int gz = blockIdx.z;
    int b = gz / NOCG, g = gz % NOCG;
    int w0 = blockIdx.x * 16, h0 = blockIdx.y * 8;

    const float* srcb = src + (size_t)b*CPAIRS*HWD*2;
    const float* wg   = wpk + (size_t)g*CPAIRS*180;
    unsigned tile_u = (unsigned)__cvta_generic_to_shared(&tile[0][0]);
    unsigned wsh_u  = (unsigned)__cvta_generic_to_shared(&wsh[0][0]);

    // Per-thread cell geometry (constant across steps).
    int hi0 = tid / 18,        wi0 = tid % 18;
    int c1i = tid + 128;
    int hi1 = c1i / 18,        wi1 = c1i % 18;
    int h0a = h0 - 1 + hi0,    w0a = w0 - 1 + wi0;
    int h1a = h0 - 1 + hi1,    w1a = w0 - 1 + wi1;
    bool v0 = ((unsigned)h0a < HH) && ((unsigned)w0a < WW);
    bool v1 = (c1i < 180) && ((unsigned)h1a < HH) && ((unsigned)w1a < WW);
    bool has1 = (c1i < 180);
    size_t go0 = v0 ? (size_t)(h0a*WW + w0a)*18 : 0;  // floats into [p][c] slab
    size_t go1 = v1 ? (size_t)(h1a*WW + w1a)*18 : 0;
    unsigned so0 = (unsigned)(tid  * 28) * 4;
    unsigned so1 = (unsigned)(c1i * 28) * 4;

    auto issue = [&](int cpi) {
        int buf = cpi & 1;
        const float* cb = srcb + (size_t)cpi*HWD*2;
        unsigned sbase = tile_u + buf*(180*28*4);
        const float* gp0 = cb + go0;
        const float* gp1 = cb + go1;
#pragma unroll
        for (int z = 0; z < 9; z++)
            cpa8(sbase + so0 + (unsigned)z*8, gp0 + 2*z, v0);
        if (has1) {
#pragma unroll
            for (int z = 0; z < 9; z++)
                cpa8(sbase + so1 + (unsigned)z*8, gp1 + 2*z, v1);
        }
        const float* wsrc = wg + (size_t)cpi*180;
        unsigned wbase = wsh_u + buf*(180*4);
        if (tid < 90)
            cpa8(wbase + (unsigned)tid*8, wsrc + 2*tid, true);
        cpa_commit();
    };

    u64 acc[3][9];
#pragma unroll
    for (int o = 0; o < 3; o++)
#pragma unroll
        for (int d = 0; d < 9; d++) acc[o][d] = 0ull;

    issue(0);

    int gstart = (tid >> 5) << 1;    // 0,2,4,6 — per-warp group rotation
    int cellbase = (ty*18 + tx)*28;  // floats

    for (int s = 0; s < CPAIRS; s++) {
        asm volatile("cp.async.wait_group 0;");   // group s landed
        __syncthreads();
        // Single barrier: publishes group s AND proves all warps finished
        // step s-1 (which read buf (s+1)&1), so that buf is free to refill.
        if (s + 1 < CPAIRS) issue(s + 1);

        int cur = s & 1;
        const float* tb = tile[cur];
        const float* wsb = wsh[cur];
#pragma unroll
        for (int gi = 0; gi < 9; gi++) {
            int grp = gstart + gi; if (grp >= 9) grp -= 9;
            int k0 = grp / 3;
            int k1 = grp - 3*k0;

            const ulonglong2* wq = (const ulonglong2*)(wsb + grp*20);
            const ulonglong2* xq =
                (const ulonglong2*)(tb + cellbase + (k0*18 + k1)*28);

            // Consume LDS.128 pairs directly (minimal live registers).
            ulonglong2 wA = wq[0];            // w[k2=0][o0], w[k2=0][o1]
            ulonglong2 wB = wq[1];            // w[k2=0][o2], w[k2=1][o0]
            ulonglong2 wC = wq[2];            // w[k2=1][o1], w[k2=1][o2]
            ulonglong2 wD = wq[3];            // w[k2=2][o0], w[k2=2][o1]
            u64 w8v = ((const u64*)wq)[8];    // w[k2=2][o2]

            ulonglong2 xp;
#pragma unroll
            for (int zp = 0; zp < 4; zp++) {   // z pairs (1,2),(3,4),(5,6),(7,8)
                xp = xq[zp];
                int z0 = 2*zp + 1, z1 = 2*zp + 2;
                // z0 taps
                { u64 xv = xp.x;
                  fma2(acc[0][z0-0>8?8:z0], wA.x, xv);        // k2=0,d=z0
                  fma2(acc[1][z0], wA.y, xv);
                  fma2(acc[2][z0], wB.x, xv);
                  if (z0 >= 1) { fma2(acc[0][z0-1], wB.y, xv);
                                 fma2(acc[1][z0-1], wC.x, xv);
                                 fma2(acc[2][z0-1], wC.y, xv); }
                  if (z0 >= 2) { fma2(acc[0][z0-2], wD.x, xv);
                                 fma2(acc[1][z0-2], wD.y, xv);
                                 fma2(acc[2][z0-2], w8v,  xv); } }
                // z1 taps
                { u64 xv = xp.y;
                  if (z1 <= 8) { fma2(acc[0][z1], wA.x, xv);
                                 fma2(acc[1][z1], wA.y, xv);
                                 fma2(acc[2][z1], wB.x, xv); }
                  fma2(acc[0][z1-1], wB.y, xv);
                  fma2(acc[1][z1-1], wC.x, xv);
                  fma2(acc[2][z1-1], wC.y, xv);
                  if (z1 >= 2) { fma2(acc[0][z1-2], wD.x, xv);
                                 fma2(acc[1][z1-2], wD.y, xv);
                                 fma2(acc[2][z1-2], w8v,  xv); } }
            }
            { u64 xv = ((const u64*)xq)[8];    // z = 9
              fma2(acc[0][8], wB.y, xv);       // k2=1,d=8
              fma2(acc[1][8], wC.x, xv);
              fma2(acc[2][8], wC.y, xv);
              fma2(acc[0][7], wD.x, xv);       // k2=2,d=7
              fma2(acc[1][7], wD.y, xv);
              fma2(acc[2][7], w8v,  xv); }
        }
    }

    int h = h0 + ty, w = w0 + tx;
    int pix = h*WW + w;
#pragma unroll
    for (int o = 0; o < 3; o++) {
        int oc = g*3 + o;
        float s  = gam[oc] * rsqrtf(var[oc] + EPSBN);
        float bi = (bias[oc] - mu[oc]) * s + bet[oc];
#pragma unroll
        for (int d = 0; d < 9; d++) {
            float lo, hi;
            upk2(lo, hi, acc[o][d]);
            float y = (lo + hi)*s + bi;
            if (FIRST) {
                y = fmaxf(y, 0.f);
                g_h12[(((size_t)(b*9 + (oc >> 1))*HWD) + pix*9 + d)*2 + (oc & 1)] = y;
            } else {
                float xg = g_xg[b*MM + oc];
                y = 1.f / (1.f + expf(-(y + xg)));
                g_wei[(size_t)(b*MM + oc)*HWD + pix*9 + d] = y;
            }
        }
    }
}

// ---------------------------------------------------------------------------
// K6: conv_last GEMM, oc-split (grid.z=2), on-the-fly A from interleaved cv,
// software-prefetched LDG.
// ---------------------------------------------------------------------------
extern __shared__ float sfin[];
__global__ __launch_bounds__(256, 2) void k_final(
        const float* __restrict__ clw, const float* __restrict__ clb,
        float* __restrict__ out) {
    float* Ws   = sfin;               // [144][80], slot j -> oc = oc0+j
    float* weis = sfin + 144*80;      // [9][128]
    int b   = blockIdx.y;
    int p0  = blockIdx.x * 128;
    int oc0 = blockIdx.z * 76;
    int jmax = (blockIdx.z == 0) ? 76 : 74;
    int tid = threadIdx.x;

    for (int t = tid; t < 80*144; t += 256) {
        int k = t % 144, j = t / 144;       // k-coalesced LDG
        int oc = oc0 + j;
        Ws[k*80 + j] = (oc < OUTC) ? clw[oc*MCC + k] : 0.f;
    }
    for (int t = tid; t < 9*128; t += 256) {
        int m = t >> 7, p = t & 127;
        weis[t] = g_wei[(size_t)(b*MM + m)*HWD + p0 + p];
    }
    __syncthreads();

    int tx = tid & 31, ty = tid >> 5;
    u64 acc[5][4];
#pragma unroll
    for (int j = 0; j < 5; j++)
#pragma unroll
        for (int i = 0; i < 4; i++) acc[j][i] = 0ull;

    const float* cvb = g_cv2 + ((size_t)b*72*HWD + (size_t)(p0 + tx*4))*2;

    float4 L0 = *(const float4*)(cvb);
    float4 L1 = *(const float4*)(cvb + 4);

    for (int cp = 0; cp < 72; cp++) {
        float4 P0 = make_float4(0.f,0.f,0.f,0.f), P1 = P0;
        if (cp < 71) {
            const float* nxt = cvb + (size_t)(cp + 1)*HWD*2;
            P0 = *(const float4*)(nxt);
            P1 = *(const float4*)(nxt + 4);
        }
        float4 wp = *(const float4*)(weis + (cp >> 3)*128 + tx*4);
        u64 e0 = pk2(L0.x*wp.x, L0.x*wp.x), e1 = pk2(L0.z*wp.y, L0.z*wp.y);
        u64 e2 = pk2(L1.x*wp.z, L1.x*wp.z), e3 = pk2(L1.z*wp.w, L1.z*wp.w);
        const u64* wr0 = (const u64*)(Ws + (2*cp)*80) + ty*5;
#pragma unroll
        for (int j = 0; j < 5; j++) {
            u64 wv = wr0[j];
            fma2(acc[j][0], wv, e0); fma2(acc[j][1], wv, e1);
            fma2(acc[j][2], wv, e2); fma2(acc[j][3], wv, e3);
        }
        u64 o0 = pk2(L0.y*wp.x, L0.y*wp.x), o1 = pk2(L0.w*wp.y, L0.w*wp.y);
        u64 o2 = pk2(L1.y*wp.z, L1.y*wp.z), o3 = pk2(L1.w*wp.w, L1.w*wp.w);
        const u64* wr1 = (const u64*)(Ws + (2*cp + 1)*80) + ty*5;
#pragma unroll
        for (int j = 0; j < 5; j++) {
            u64 wv = wr1[j];
            fma2(acc[j][0], wv, o0); fma2(acc[j][1], wv, o1);
            fma2(acc[j][2], wv, o2); fma2(acc[j][3], wv, o3);
        }
        L0 = P0; L1 = P1;
    }

#pragma unroll
    for (int j = 0; j < 5; j++) {
        int j0 = ty*10 + 2*j;
        float lo[4], hi[4];
#pragma unroll
        for (int i = 0; i < 4; i++) upk2(lo[i], hi[i], acc[j][i]);
        if (j0 < jmax) {
            int oc = oc0 + j0;
            float bv = clb[oc];
            float4 r = make_float4(lo[0]+bv, lo[1]+bv, lo[2]+bv, lo[3]+bv);
            *(float4*)(out + (size_t)(b*OUTC + oc)*HWD + p0 + tx*4) = r;
        }
        if (j0 + 1 < jmax) {
            int oc = oc0 + j0 + 1;
            float bv = clb[oc];
            float4 r = make_float4(hi[0]+bv, hi[1]+bv, hi[2]+bv, hi[3]+bv);
            *(float4*)(out + (size_t)(b*OUTC + oc)*HWD + p0 + tx*4) = r;
        }
    }
}

// ---------------------------------------------------------------------------
extern "C" void kernel_launch(void* const* d_in, const int* in_sizes, int n_in,
                              void* d_out, int out_size) {
    const float* x      = (const float*)d_in[0];
    const float* la_w1  = (const float*)d_in[1];
    const float* la_b1  = (const float*)d_in[2];
    const float* la_g1  = (const float*)d_in[3];
    const float* la_be1 = (const float*)d_in[4];
    const float* la_m1  = (const float*)d_in[5];
    const float* la_v1  = (const float*)d_in[6];
    const float* la_w2  = (const float*)d_in[7];
    const float* la_b2  = (const float*)d_in[8];
    const float* la_g2  = (const float*)d_in[9];
    const float* la_be2 = (const float*)d_in[10];
    const float* la_m2  = (const float*)d_in[11];
    const float* la_v2  = (const float*)d_in[12];
    const float* ga_w1  = (const float*)d_in[13];
    const float* ga_b1  = (const float*)d_in[14];
    const float* ga_g1  = (const float*)d_in[15];
    const float* ga_be1 = (const float*)d_in[16];
    const float* ga_m1  = (const float*)d_in[17];
    const float* ga_v1  = (const float*)d_in[18];
    const float* ga_w2  = (const float*)d_in[19];
    const float* ga_b2  = (const float*)d_in[20];
    const float* ga_g2  = (const float*)d_in[21];
    const float* ga_be2 = (const float*)d_in[22];
    const float* ga_m2  = (const float*)d_in[23];
    const float* ga_v2  = (const float*)d_in[24];
    const float* cl_w   = (const float*)d_in[25];
    const float* cl_b   = (const float*)d_in[26];
    float* out = (float*)d_out;

    // Launch order: conv1 at index 3 (profiler captures idx 3).
    k_packw<<<(HIDN*MCC*27 + 255)/256, 256>>>(la_w1, la_w2);              // 0
    unsigned ncell = BB*72*HW;
    k_build_cv<<<(ncell + 255)/256, 256>>>(x);                             // 1
    k_reduce<<<BB*MCC, 256>>>(x);                                          // 2

    dim3 g1(WW/16, HH/8, BB*6);
    k_conv<72, 6, true><<<g1, 128>>>(la_g1, la_be1, la_m1, la_v1, la_b1);  // 3

    k_global<<<1, 64>>>(ga_w1, ga_b1, ga_g1, ga_be1, ga_m1, ga_v1,
                        ga_w2, ga_b2, ga_g2, ga_be2, ga_m2, ga_v2);        // 4

    dim3 g2(WW/16, HH/8, BB*3);
    k_conv<9, 3, false><<<g2, 128>>>(la_g2, la_be2, la_m2, la_v2, la_b2);  // 5

    const int smem_fin = (144*80 + 9*128) * 4;   // 50688
    cudaFuncSetAttribute(k_final, cudaFuncAttributeMaxDynamicSharedMemorySize, smem_fin);
    dim3 gf(HWD/128, BB, 2);
    k_final<<<gf, 256, smem_fin>>>(cl_w, cl_b, out);                       // 6
}

// round 16
// speedup vs baseline: 1.0331x; 1.0331x over previous
#include <cuda_runtime.h>
#include <math.h>

// Problem dims
#define BB   2
#define CCH  16
#define HH   128
#define WW   128
#define MM   9
#define NDD  9
#define MCC  144
#define HIDN 18
#define OUTC 150
#define HW   (HH*WW)       // 16384
#define HWD  (HH*WW*NDD)   // 147456
#define EPSBN 1e-5f

// Scratch (device globals). Channel-pair interleaved layouts:
// g_cv2[b][cp][p][c] : cp=0..71, p=pix*9+d, c=channel parity (pairs adjacent)
__device__ float g_cv2[BB*(size_t)72*HWD*2];
__device__ float g_h12[BB*(size_t)9*HWD*2];   // hidden, 9 cpairs interleaved
__device__ float g_wei[BB*(size_t)MM*HWD];    // sigmoid attention (plain)
__device__ float g_p  [BB*MCC];               // global mean pool
__device__ float g_xg [BB*MM];                // global-branch logits
// conv weights: [g][cpair][grp=k0*3+k1][20]: floats 0..17 = (k2*3+o)*2+par, 18-19 pad
__device__ float g_w1p[6*72*180];
__device__ float g_w2p[3*9*180];

typedef unsigned long long u64;

__device__ __forceinline__ void upk2(float &lo, float &hi, u64 v) {
    unsigned a, b;
    asm("mov.b64 {%0, %1}, %2;" : "=r"(a), "=r"(b) : "l"(v));
    lo = __uint_as_float(a); hi = __uint_as_float(b);
}
__device__ __forceinline__ void fma2(u64 &d, u64 a, u64 b) {
    asm("fma.rn.f32x2 %0, %1, %2, %0;" : "+l"(d) : "l"(a), "l"(b));
}
__device__ __forceinline__ u64 pk2(float lo, float hi) {
    u64 r;
    asm("mov.b64 %0, {%1, %2};" : "=l"(r) : "r"(__float_as_uint(lo)), "r"(__float_as_uint(hi)));
    return r;
}
__device__ __forceinline__ void cpa8(unsigned saddr, const void* gaddr, bool valid) {
    int sz = valid ? 8 : 0;   // src-size 0 -> zero-fill
    asm volatile("cp.async.ca.shared.global [%0], [%1], 8, %2;"
                 :: "r"(saddr), "l"(gaddr), "r"(sz));
}
__device__ __forceinline__ void cpa_commit() {
    asm volatile("cp.async.commit_group;");
}

// ---------------------------------------------------------------------------
// K-pack: channel-pair interleave conv weights, 80B-aligned tap groups.
// ---------------------------------------------------------------------------
__global__ void k_packw(const float* __restrict__ w1, const float* __restrict__ w2) {
    int t = blockIdx.x * 256 + threadIdx.x;
    if (t < HIDN*MCC*27) {
        int tap = t % 27; int r = t / 27;
        int ch = r % MCC; int oc = r / MCC;
        int k0 = tap / 9, k1 = (tap / 3) % 3, k2 = tap % 3;
        int g = oc / 3, o = oc % 3;
        int cp = ch >> 1, par = ch & 1;
        float v = w1[((size_t)oc*MCC + ch)*27 + tap];
        g_w1p[(((size_t)(g*72 + cp)*9 + (k0*3 + k1))*20) + (k2*3 + o)*2 + par] = v;
    }
    if (t < MM*HIDN*27) {
        int tap = t % 27; int r = t / 27;
        int ch = r % HIDN; int oc = r / HIDN;
        int k0 = tap / 9, k1 = (tap / 3) % 3, k2 = tap % 3;
        int g = oc / 3, o = oc % 3;
        int cp = ch >> 1, par = ch & 1;
        float v = w2[((size_t)oc*HIDN + ch)*27 + tap];
        g_w2p[(((size_t)(g*9 + cp)*9 + (k0*3 + k1))*20) + (k2*3 + o)*2 + par] = v;
    }
}

// ---------------------------------------------------------------------------
// K1: build cost volume, channel-pair interleaved. One thread per (b,cp,pix).
// ---------------------------------------------------------------------------
__global__ void k_build_cv(const float* __restrict__ x) {
    unsigned idx = blockIdx.x * 256 + threadIdx.x;
    if (idx >= (unsigned)(BB*72*HW)) return;
    unsigned i = idx;
    int pix = i % HW;  i /= HW;
    int cp  = i % 72;
    int b   = i / 72;
    int mc0 = 2*cp;
    int m = mc0 / CCH, ch = mc0 % CCH;
    int w = pix & 127, h = pix >> 7;
    int s = m - 4;
    const float* x0 = x + ((size_t)(b*CCH + ch)*HW + h*WW)*MM + m;
    const float* x1 = x0 + (size_t)HW*MM;   // channel ch+1, same m
    float2* dst = ((float2*)g_cv2) + ((size_t)(b*72 + cp)*HWD + (size_t)pix*9);
#pragma unroll
    for (int d = 0; d < 9; d++) {
        int ws = w + (d - 4)*s;
        float2 v = make_float2(0.f, 0.f);
        if ((unsigned)ws < WW) {
            v.x = x0[(size_t)ws*MM];
            v.y = x1[(size_t)ws*MM];
        }
        dst[d] = v;
    }
}

// ---------------------------------------------------------------------------
// K2: mean pool per (b,mc) computed directly from x with shift multiplicity.
// ---------------------------------------------------------------------------
__global__ void k_reduce(const float* __restrict__ x) {
    int bm = blockIdx.x;                 // 0..287
    int b = bm / MCC, mc = bm % MCC;
    int m = mc / CCH, ch = mc % CCH;
    int s = m - 4;
    const float* xb = x + ((size_t)(b*CCH + ch)*HW)*MM + m;
    float sum = 0.f;
    for (int i = threadIdx.x; i < HW; i += 256) {
        int wp = i & 127;
        int cnt = 0;
#pragma unroll
        for (int d = 0; d < 9; d++) {
            int wsrc = wp - (d - 4)*s;
            cnt += ((unsigned)wsrc < WW) ? 1 : 0;
        }
        sum += xb[(size_t)i*MM] * (float)cnt;
    }
    __shared__ float sh[256];
    sh[threadIdx.x] = sum;
    __syncthreads();
    for (int o = 128; o > 0; o >>= 1) {
        if (threadIdx.x < o) sh[threadIdx.x] += sh[threadIdx.x + o];
        __syncthreads();
    }
    if (threadIdx.x == 0) g_p[bm] = sh[0] * (1.0f / HWD);
}

// ---------------------------------------------------------------------------
// K3: global attention branch (center tap only at 1x1x1 spatial).
// ---------------------------------------------------------------------------
__global__ void k_global(const float* __restrict__ w1, const float* __restrict__ b1,
                         const float* __restrict__ g1, const float* __restrict__ be1,
                         const float* __restrict__ m1, const float* __restrict__ v1,
                         const float* __restrict__ w2, const float* __restrict__ b2,
                         const float* __restrict__ g2, const float* __restrict__ be2,
                         const float* __restrict__ m2, const float* __restrict__ v2) {
    __shared__ float gh[BB*HIDN];
    int t = threadIdx.x;
    if (t < BB*HIDN) {
        int b = t / HIDN, o = t % HIDN;
        float s = b1[o];
        for (int c = 0; c < MCC; c++)
            s += w1[(o*MCC + c)*27 + 13] * g_p[b*MCC + c];
        float sc = g1[o] * rsqrtf(v1[o] + EPSBN);
        s = (s - m1[o]) * sc + be1[o];
        gh[t] = fmaxf(s, 0.f);
    }
    __syncthreads();
    if (t < BB*MM) {
        int b = t / MM, og = t % MM;
        float s = b2[og];
        for (int o = 0; o < HIDN; o++)
            s += w2[(og*HIDN + o)*27 + 13] * gh[b*HIDN + o];
        float sc = g2[og] * rsqrtf(v2[og] + EPSBN);
        g_xg[t] = (s - m2[og]) * sc + be2[og];
    }
}

// ---------------------------------------------------------------------------
// K4/K5: 3x3x3 conv (EXACT R13 best-measured body): f32x2 channel-pair,
// cp.async.8 2-buffer pipeline, ONE barrier per step, staged w_/xs arrays,
// warp-staggered group order. Cell = 28 floats (112B, conflict-free).
// Block 128 = 16(w) x 8(h). grid z = B*NOCG (3 oc per group).
// ---------------------------------------------------------------------------
template<int CPAIRS, int NOCG, bool FIRST>
__global__ __launch_bounds__(128, 4) void k_conv(
        const float* __restrict__ gam, const float* __restrict__ bet,
        const float* __restrict__ mu,  const float* __restrict__ var,
        const float* __restrict__ bias) {
    __shared__ __align__(16) float tile[2][180*28];
    __shared__ __align__(16) float wsh[2][180];

    const float* src = FIRST ? g_cv2 : g_h12;
    const float* wpk = FIRST ? g_w1p : g_w2p;

    int tid = threadIdx.x;
    int tx = tid & 15, ty = tid >> 4;        // 16 x 8
    int gz = blockIdx.z;
    int b = gz / NOCG, g = gz % NOCG;
    int w0 = blockIdx.x * 16, h0 = blockIdx.y * 8;

    const float* srcb = src + (size_t)b*CPAIRS*HWD*2;
    const float* wg   = wpk + (size_t)g*CPAIRS*180;
    unsigned tile_u = (unsigned)__cvta_generic_to_shared(&tile[0][0]);
    unsigned wsh_u  = (unsigned)__cvta_generic_to_shared(&wsh[0][0]);

    // Per-thread cell geometry (constant across steps).
    int hi0 = tid / 18,        wi0 = tid % 18;
    int c1i = tid + 128;
    int hi1 = c1i / 18,        wi1 = c1i % 18;
    int h0a = h0 - 1 + hi0,    w0a = w0 - 1 + wi0;
    int h1a = h0 - 1 + hi1,    w1a = w0 - 1 + wi1;
    bool v0 = ((unsigned)h0a < HH) && ((unsigned)w0a < WW);
    bool v1 = (c1i < 180) && ((unsigned)h1a < HH) && ((unsigned)w1a < WW);
    bool has1 = (c1i < 180);
    size_t go0 = v0 ? (size_t)(h0a*WW + w0a)*18 : 0;  // floats into [p][c] slab
    size_t go1 = v1 ? (size_t)(h1a*WW + w1a)*18 : 0;
    unsigned so0 = (unsigned)(tid  * 28) * 4;
    unsigned so1 = (unsigned)(c1i * 28) * 4;

    auto issue = [&](int cpi) {
        int buf = cpi & 1;
        const float* cb = srcb + (size_t)cpi*HWD*2;
        unsigned sbase = tile_u + buf*(180*28*4);
        const float* gp0 = cb + go0;
        const float* gp1 = cb + go1;
#pragma unroll
        for (int z = 0; z < 9; z++)
            cpa8(sbase + so0 + (unsigned)z*8, gp0 + 2*z, v0);
        if (has1) {
#pragma unroll
            for (int z = 0; z < 9; z++)
                cpa8(sbase + so1 + (unsigned)z*8, gp1 + 2*z, v1);
        }
        const float* wsrc = wg + (size_t)cpi*180;
        unsigned wbase = wsh_u + buf*(180*4);
        if (tid < 90)
            cpa8(wbase + (unsigned)tid*8, wsrc + 2*tid, true);
        cpa_commit();
    };

    u64 acc[3][9];
#pragma unroll
    for (int o = 0; o < 3; o++)
#pragma unroll
        for (int d = 0; d < 9; d++) acc[o][d] = 0ull;

    issue(0);

    int gstart = (tid >> 5) << 1;    // 0,2,4,6 — per-warp group rotation
    int cellbase = (ty*18 + tx)*28;  // floats

    for (int s = 0; s < CPAIRS; s++) {
        asm volatile("cp.async.wait_group 0;");   // group s landed
        __syncthreads();
        // Single barrier: publishes group s AND proves all warps finished
        // step s-1 (which read buf (s+1)&1), so that buf is free to refill.
        if (s + 1 < CPAIRS) issue(s + 1);

        int cur = s & 1;
        const float* tb = tile[cur];
        const float* wsb = wsh[cur];
#pragma unroll
        for (int gi = 0; gi < 9; gi++) {
            int grp = gstart + gi; if (grp >= 9) grp -= 9;
            int k0 = grp / 3;
            int k1 = grp - 3*k0;

            const ulonglong2* wq = (const ulonglong2*)(wsb + grp*20);
            ulonglong2 wA = wq[0], wB = wq[1], wC = wq[2], wD = wq[3];
            u64 w8v = ((const u64*)wq)[8];
            u64 w_[9] = {wA.x, wA.y, wB.x, wB.y, wC.x, wC.y, wD.x, wD.y, w8v};

            const ulonglong2* xq =
                (const ulonglong2*)(tb + cellbase + (k0*18 + k1)*28);
            ulonglong2 x12 = xq[0], x34 = xq[1], x56 = xq[2], x78 = xq[3];
            u64 x9v = ((const u64*)xq)[8];
            u64 xs[9] = {x12.x, x12.y, x34.x, x34.y, x56.x, x56.y, x78.x, x78.y, x9v};

#pragma unroll
            for (int z = 1; z <= 9; z++) {
                u64 xv = xs[z - 1];
#pragma unroll
                for (int k2 = 0; k2 < 3; k2++) {
                    int d = z - k2;
                    if (d >= 0 && d <= 8) {
#pragma unroll
                        for (int o = 0; o < 3; o++)
                            fma2(acc[o][d], w_[k2*3 + o], xv);
                    }
                }
            }
        }
    }

    int h = h0 + ty, w = w0 + tx;
    int pix = h*WW + w;
#pragma unroll
    for (int o = 0; o < 3; o++) {
        int oc = g*3 + o;
        float s  = gam[oc] * rsqrtf(var[oc] + EPSBN);
        float bi = (bias[oc] - mu[oc]) * s + bet[oc];
#pragma unroll
        for (int d = 0; d < 9; d++) {
            float lo, hi;
            upk2(lo, hi, acc[o][d]);
            float y = (lo + hi)*s + bi;
            if (FIRST) {
                y = fmaxf(y, 0.f);
                g_h12[(((size_t)(b*9 + (oc >> 1))*HWD) + pix*9 + d)*2 + (oc & 1)] = y;
            } else {
                float xg = g_xg[b*MM + oc];
                y = 1.f / (1.f + expf(-(y + xg)));
                g_wei[(size_t)(b*MM + oc)*HWD + pix*9 + d] = y;
            }
        }
    }
}

// ---------------------------------------------------------------------------
// K6: conv_last GEMM, oc-split (grid.z=2), on-the-fly A from interleaved cv,
// software-prefetched LDG. __launch_bounds__(256,3): 85-reg cap -> 3 blocks/SM
// (24 warps) to cover the FMUL->pk2->FMA2 latency chain; smem 3x50.7KB fits.
// ---------------------------------------------------------------------------
extern __shared__ float sfin[];
__global__ __launch_bounds__(256, 3) void k_final(
        const float* __restrict__ clw, const float* __restrict__ clb,
        float* __restrict__ out) {
    float* Ws   = sfin;               // [144][80], slot j -> oc = oc0+j
    float* weis = sfin + 144*80;      // [9][128]
    int b   = blockIdx.y;
    int p0  = blockIdx.x * 128;
    int oc0 = blockIdx.z * 76;
    int jmax = (blockIdx.z == 0) ? 76 : 74;
    int tid = threadIdx.x;

    for (int t = tid; t < 80*144; t += 256) {
        int k = t % 144, j = t / 144;       // k-coalesced LDG
        int oc = oc0 + j;
        Ws[k*80 + j] = (oc < OUTC) ? clw[oc*MCC + k] : 0.f;
    }
    for (int t = tid; t < 9*128; t += 256) {
        int m = t >> 7, p = t & 127;
        weis[t] = g_wei[(size_t)(b*MM + m)*HWD + p0 + p];
    }
    __syncthreads();

    int tx = tid & 31, ty = tid >> 5;
    u64 acc[5][4];
#pragma unroll
    for (int j = 0; j < 5; j++)
#pragma unroll
        for (int i = 0; i < 4; i++) acc[j][i] = 0ull;

    const float* cvb = g_cv2 + ((size_t)b*72*HWD + (size_t)(p0 + tx*4))*2;

    float4 L0 = *(const float4*)(cvb);
    float4 L1 = *(const float4*)(cvb + 4);

    for (int cp = 0; cp < 72; cp++) {
        float4 P0 = make_float4(0.f,0.f,0.f,0.f), P1 = P0;
        if (cp < 71) {
            const float* nxt = cvb + (size_t)(cp + 1)*HWD*2;
            P0 = *(const float4*)(nxt);
            P1 = *(const float4*)(nxt + 4);
        }
        float4 wp = *(const float4*)(weis + (cp >> 3)*128 + tx*4);
        u64 e0 = pk2(L0.x*wp.x, L0.x*wp.x), e1 = pk2(L0.z*wp.y, L0.z*wp.y);
        u64 e2 = pk2(L1.x*wp.z, L1.x*wp.z), e3 = pk2(L1.z*wp.w, L1.z*wp.w);
        const u64* wr0 = (const u64*)(Ws + (2*cp)*80) + ty*5;
#pragma unroll
        for (int j = 0; j < 5; j++) {
            u64 wv = wr0[j];
            fma2(acc[j][0], wv, e0); fma2(acc[j][1], wv, e1);
            fma2(acc[j][2], wv, e2); fma2(acc[j][3], wv, e3);
        }
        u64 o0 = pk2(L0.y*wp.x, L0.y*wp.x), o1 = pk2(L0.w*wp.y, L0.w*wp.y);
        u64 o2 = pk2(L1.y*wp.z, L1.y*wp.z), o3 = pk2(L1.w*wp.w, L1.w*wp.w);
        const u64* wr1 = (const u64*)(Ws + (2*cp + 1)*80) + ty*5;
#pragma unroll
        for (int j = 0; j < 5; j++) {
            u64 wv = wr1[j];
            fma2(acc[j][0], wv, o0); fma2(acc[j][1], wv, o1);
            fma2(acc[j][2], wv, o2); fma2(acc[j][3], wv, o3);
        }
        L0 = P0; L1 = P1;
    }

#pragma unroll
    for (int j = 0; j < 5; j++) {
        int j0 = ty*10 + 2*j;
        float lo[4], hi[4];
#pragma unroll
        for (int i = 0; i < 4; i++) upk2(lo[i], hi[i], acc[j][i]);
        if (j0 < jmax) {
            int oc = oc0 + j0;
            float bv = clb[oc];
            float4 r = make_float4(lo[0]+bv, lo[1]+bv, lo[2]+bv, lo[3]+bv);
            *(float4*)(out + (size_t)(b*OUTC + oc)*HWD + p0 + tx*4) = r;
        }
        if (j0 + 1 < jmax) {
            int oc = oc0 + j0 + 1;
            float bv = clb[oc];
            float4 r = make_float4(hi[0]+bv, hi[1]+bv, hi[2]+bv, hi[3]+bv);
            *(float4*)(out + (size_t)(b*OUTC + oc)*HWD + p0 + tx*4) = r;
        }
    }
}

// ---------------------------------------------------------------------------
extern "C" void kernel_launch(void* const* d_in, const int* in_sizes, int n_in,
                              void* d_out, int out_size) {
    const float* x      = (const float*)d_in[0];
    const float* la_w1  = (const float*)d_in[1];
    const float* la_b1  = (const float*)d_in[2];
    const float* la_g1  = (const float*)d_in[3];
    const float* la_be1 = (const float*)d_in[4];
    const float* la_m1  = (const float*)d_in[5];
    const float* la_v1  = (const float*)d_in[6];
    const float* la_w2  = (const float*)d_in[7];
    const float* la_b2  = (const float*)d_in[8];
    const float* la_g2  = (const float*)d_in[9];
    const float* la_be2 = (const float*)d_in[10];
    const float* la_m2  = (const float*)d_in[11];
    const float* la_v2  = (const float*)d_in[12];
    const float* ga_w1  = (const float*)d_in[13];
    const float* ga_b1  = (const float*)d_in[14];
    const float* ga_g1  = (const float*)d_in[15];
    const float* ga_be1 = (const float*)d_in[16];
    const float* ga_m1  = (const float*)d_in[17];
    const float* ga_v1  = (const float*)d_in[18];
    const float* ga_w2  = (const float*)d_in[19];
    const float* ga_b2  = (const float*)d_in[20];
    const float* ga_g2  = (const float*)d_in[21];
    const float* ga_be2 = (const float*)d_in[22];
    const float* ga_m2  = (const float*)d_in[23];
    const float* ga_v2  = (const float*)d_in[24];
    const float* cl_w   = (const float*)d_in[25];
    const float* cl_b   = (const float*)d_in[26];
    float* out = (float*)d_out;

    // Launch order: conv1 at index 3 (profiler captures idx 3).
    k_packw<<<(HIDN*MCC*27 + 255)/256, 256>>>(la_w1, la_w2);              // 0
    unsigned ncell = BB*72*HW;
    k_build_cv<<<(ncell + 255)/256, 256>>>(x);                             // 1
    k_reduce<<<BB*MCC, 256>>>(x);                                          // 2

    dim3 g1(WW/16, HH/8, BB*6);
    k_conv<72, 6, true><<<g1, 128>>>(la_g1, la_be1, la_m1, la_v1, la_b1);  // 3

    k_global<<<1, 64>>>(ga_w1, ga_b1, ga_g1, ga_be1, ga_m1, ga_v1,
                        ga_w2, ga_b2, ga_g2, ga_be2, ga_m2, ga_v2);        // 4

    dim3 g2(WW/16, HH/8, BB*3);
    k_conv<9, 3, false><<<g2, 128>>>(la_g2, la_be2, la_m2, la_v2, la_b2);  // 5

    const int smem_fin = (144*80 + 9*128) * 4;   // 50688
    cudaFuncSetAttribute(k_final, cudaFuncAttributeMaxDynamicSharedMemorySize, smem_fin);
    dim3 gf(HWD/128, BB, 2);
    k_final<<<gf, 256, smem_fin>>>(cl_w, cl_b, out);                       // 6
}

// round 17
// speedup vs baseline: 1.0617x; 1.0277x over previous
#include <cuda_runtime.h>
#include <math.h>

// Problem dims
#define BB   2
#define CCH  16
#define HH   128
#define WW   128
#define MM   9
#define NDD  9
#define MCC  144
#define HIDN 18
#define OUTC 150
#define HW   (HH*WW)       // 16384
#define HWD  (HH*WW*NDD)   // 147456
#define EPSBN 1e-5f

// Scratch (device globals). Channel-pair interleaved layouts:
// g_cv2[b][cp][p][c] : cp=0..71, p=pix*9+d, c=channel parity (pairs adjacent)
__device__ float g_cv2[BB*(size_t)72*HWD*2];
__device__ float g_h12[BB*(size_t)9*HWD*2];   // hidden, 9 cpairs interleaved
__device__ float g_wei[BB*(size_t)MM*HWD];    // sigmoid attention (plain)
__device__ float g_p  [BB*MCC];               // global mean pool
__device__ float g_xg [BB*MM];                // global-branch logits
// conv1 weights: OCB=6 -> [g(3)][cpair(72)][grp(9)][40]:
//   floats t*20 + (k2*3+o)*2 + par  (t = oc-triple 0/1, pads 18,19,38,39)
__device__ float g_w1p[3*72*9*40];
// conv2 weights: OCB=3 -> [g(3)][cpair(9)][grp(9)][20]
__device__ float g_w2p[3*9*9*20];

typedef unsigned long long u64;

__device__ __forceinline__ void upk2(float &lo, float &hi, u64 v) {
    unsigned a, b;
    asm("mov.b64 {%0, %1}, %2;" : "=r"(a), "=r"(b) : "l"(v));
    lo = __uint_as_float(a); hi = __uint_as_float(b);
}
__device__ __forceinline__ void fma2(u64 &d, u64 a, u64 b) {
    asm("fma.rn.f32x2 %0, %1, %2, %0;" : "+l"(d) : "l"(a), "l"(b));
}
__device__ __forceinline__ u64 pk2(float lo, float hi) {
    u64 r;
    asm("mov.b64 %0, {%1, %2};" : "=l"(r) : "r"(__float_as_uint(lo)), "r"(__float_as_uint(hi)));
    return r;
}
__device__ __forceinline__ void cpa8(unsigned saddr, const void* gaddr, bool valid) {
    int sz = valid ? 8 : 0;   // src-size 0 -> zero-fill
    asm volatile("cp.async.ca.shared.global [%0], [%1], 8, %2;"
                 :: "r"(saddr), "l"(gaddr), "r"(sz));
}
__device__ __forceinline__ void cpa_commit() {
    asm volatile("cp.async.commit_group;");
}

// ---------------------------------------------------------------------------
// K-pack: channel-pair interleave conv weights.
// conv1: 6-oc groups (40-float tap groups); conv2: 3-oc (20-float).
// ---------------------------------------------------------------------------
__global__ void k_packw(const float* __restrict__ w1, const float* __restrict__ w2) {
    int t = blockIdx.x * 256 + threadIdx.x;
    if (t < HIDN*MCC*27) {
        int tap = t % 27; int r = t / 27;
        int ch = r % MCC; int oc = r / MCC;
        int k0 = tap / 9, k1 = (tap / 3) % 3, k2 = tap % 3;
        int g = oc / 6, o6 = oc % 6;
        int tt = o6 / 3, o = o6 % 3;
        int cp = ch >> 1, par = ch & 1;
        float v = w1[((size_t)oc*MCC + ch)*27 + tap];
        g_w1p[(((size_t)(g*72 + cp)*9 + (k0*3 + k1))*40) + tt*20 + (k2*3 + o)*2 + par] = v;
    }
    if (t < MM*HIDN*27) {
        int tap = t % 27; int r = t / 27;
        int ch = r % HIDN; int oc = r / HIDN;
        int k0 = tap / 9, k1 = (tap / 3) % 3, k2 = tap % 3;
        int g = oc / 3, o = oc % 3;
        int cp = ch >> 1, par = ch & 1;
        float v = w2[((size_t)oc*HIDN + ch)*27 + tap];
        g_w2p[(((size_t)(g*9 + cp)*9 + (k0*3 + k1))*20) + (k2*3 + o)*2 + par] = v;
    }
}

// ---------------------------------------------------------------------------
// K1: build cost volume, channel-pair interleaved. One thread per (b,cp,pix).
// ---------------------------------------------------------------------------
__global__ void k_build_cv(const float* __restrict__ x) {
    unsigned idx = blockIdx.x * 256 + threadIdx.x;
    if (idx >= (unsigned)(BB*72*HW)) return;
    unsigned i = idx;
    int pix = i % HW;  i /= HW;
    int cp  = i % 72;
    int b   = i / 72;
    int mc0 = 2*cp;
    int m = mc0 / CCH, ch = mc0 % CCH;
    int w = pix & 127, h = pix >> 7;
    int s = m - 4;
    const float* x0 = x + ((size_t)(b*CCH + ch)*HW + h*WW)*MM + m;
    const float* x1 = x0 + (size_t)HW*MM;   // channel ch+1, same m
    float2* dst = ((float2*)g_cv2) + ((size_t)(b*72 + cp)*HWD + (size_t)pix*9);
#pragma unroll
    for (int d = 0; d < 9; d++) {
        int ws = w + (d - 4)*s;
        float2 v = make_float2(0.f, 0.f);
        if ((unsigned)ws < WW) {
            v.x = x0[(size_t)ws*MM];
            v.y = x1[(size_t)ws*MM];
        }
        dst[d] = v;
    }
}

// ---------------------------------------------------------------------------
// K2: mean pool per (b,mc) computed directly from x with shift multiplicity.
// ---------------------------------------------------------------------------
__global__ void k_reduce(const float* __restrict__ x) {
    int bm = blockIdx.x;                 // 0..287
    int b = bm / MCC, mc = bm % MCC;
    int m = mc / CCH, ch = mc % CCH;
    int s = m - 4;
    const float* xb = x + ((size_t)(b*CCH + ch)*HW)*MM + m;
    float sum = 0.f;
    for (int i = threadIdx.x; i < HW; i += 256) {
        int wp = i & 127;
        int cnt = 0;
#pragma unroll
        for (int d = 0; d < 9; d++) {
            int wsrc = wp - (d - 4)*s;
            cnt += ((unsigned)wsrc < WW) ? 1 : 0;
        }
        sum += xb[(size_t)i*MM] * (float)cnt;
    }
    __shared__ float sh[256];
    sh[threadIdx.x] = sum;
    __syncthreads();
    for (int o = 128; o > 0; o >>= 1) {
        if (threadIdx.x < o) sh[threadIdx.x] += sh[threadIdx.x + o];
        __syncthreads();
    }
    if (threadIdx.x == 0) g_p[bm] = sh[0] * (1.0f / HWD);
}

// ---------------------------------------------------------------------------
// K3: global attention branch (center tap only at 1x1x1 spatial).
// ---------------------------------------------------------------------------
__global__ void k_global(const float* __restrict__ w1, const float* __restrict__ b1,
                         const float* __restrict__ g1, const float* __restrict__ be1,
                         const float* __restrict__ m1, const float* __restrict__ v1,
                         const float* __restrict__ w2, const float* __restrict__ b2,
                         const float* __restrict__ g2, const float* __restrict__ be2,
                         const float* __restrict__ m2, const float* __restrict__ v2) {
    __shared__ float gh[BB*HIDN];
    int t = threadIdx.x;
    if (t < BB*HIDN) {
        int b = t / HIDN, o = t % HIDN;
        float s = b1[o];
        for (int c = 0; c < MCC; c++)
            s += w1[(o*MCC + c)*27 + 13] * g_p[b*MCC + c];
        float sc = g1[o] * rsqrtf(v1[o] + EPSBN);
        s = (s - m1[o]) * sc + be1[o];
        gh[t] = fmaxf(s, 0.f);
    }
    __syncthreads();
    if (t < BB*MM) {
        int b = t / MM, og = t % MM;
        float s = b2[og];
        for (int o = 0; o < HIDN; o++)
            s += w2[(og*HIDN + o)*27 + 13] * gh[b*HIDN + o];
        float sc = g2[og] * rsqrtf(v2[og] + EPSBN);
        g_xg[t] = (s - m2[og]) * sc + be2[og];
    }
}

// ---------------------------------------------------------------------------
// K4/K5: 3x3x3 conv, f32x2 channel-pair, cp.async.8 2-buffer pipeline,
// ONE barrier per step, staged xs/w_ arrays, warp-staggered groups.
// OCB = oc per thread (6 for conv1: each block serves 6 oc -> cv tile read
// 3x total instead of 6x, halving LDS+cp.async per FMA; 3 for conv2).
// Cell = 28 floats (112B, conflict-free).
// Block 128 = 16(w) x 8(h). grid z = B*NOCG.
// ---------------------------------------------------------------------------
template<int CPAIRS, int NOCG, int OCB, bool FIRST>
__global__ __launch_bounds__(128, (OCB == 6 ? 3 : 4)) void k_conv(
        const float* __restrict__ gam, const float* __restrict__ bet,
        const float* __restrict__ mu,  const float* __restrict__ var,
        const float* __restrict__ bias) {
    const int WGRP = (OCB == 6) ? 40 : 20;     // floats per (k0,k1) group
    const int WTOT = 9 * WGRP;                 // floats per cpair
    __shared__ __align__(16) float tile[2][180*28];
    __shared__ __align__(16) float wsh[2][9*((OCB == 6) ? 40 : 20)];

    const float* src = FIRST ? g_cv2 : g_h12;
    const float* wpk = FIRST ? g_w1p : g_w2p;

    int tid = threadIdx.x;
    int tx = tid & 15, ty = tid >> 4;        // 16 x 8
    int gz = blockIdx.z;
    int b = gz / NOCG, g = gz % NOCG;
    int w0 = blockIdx.x * 16, h0 = blockIdx.y * 8;

    const float* srcb = src + (size_t)b*CPAIRS*HWD*2;
    const float* wg   = wpk + (size_t)g*CPAIRS*WTOT;
    unsigned tile_u = (unsigned)__cvta_generic_to_shared(&tile[0][0]);
    unsigned wsh_u  = (unsigned)__cvta_generic_to_shared(&wsh[0][0]);

    // Per-thread cell geometry (constant across steps).
    int hi0 = tid / 18,        wi0 = tid % 18;
    int c1i = tid + 128;
    int hi1 = c1i / 18,        wi1 = c1i % 18;
    int h0a = h0 - 1 + hi0,    w0a = w0 - 1 + wi0;
    int h1a = h0 - 1 + hi1,    w1a = w0 - 1 + wi1;
    bool v0 = ((unsigned)h0a < HH) && ((unsigned)w0a < WW);
    bool v1 = (c1i < 180) && ((unsigned)h1a < HH) && ((unsigned)w1a < WW);
    bool has1 = (c1i < 180);
    size_t go0 = v0 ? (size_t)(h0a*WW + w0a)*18 : 0;  // floats into [p][c] slab
    size_t go1 = v1 ? (size_t)(h1a*WW + w1a)*18 : 0;
    unsigned so0 = (unsigned)(tid  * 28) * 4;
    unsigned so1 = (unsigned)(c1i * 28) * 4;

    auto issue = [&](int cpi) {
        int buf = cpi & 1;
        const float* cb = srcb + (size_t)cpi*HWD*2;
        unsigned sbase = tile_u + buf*(180*28*4);
        const float* gp0 = cb + go0;
        const float* gp1 = cb + go1;
#pragma unroll
        for (int z = 0; z < 9; z++)
            cpa8(sbase + so0 + (unsigned)z*8, gp0 + 2*z, v0);
        if (has1) {
#pragma unroll
            for (int z = 0; z < 9; z++)
                cpa8(sbase + so1 + (unsigned)z*8, gp1 + 2*z, v1);
        }
        const float* wsrc = wg + (size_t)cpi*WTOT;
        unsigned wbase = wsh_u + buf*(WTOT*4);
#pragma unroll
        for (int j = 0; j < (WTOT/2 + 127)/128; j++) {
            int idx = j*128 + tid;
            if (idx < WTOT/2) cpa8(wbase + (unsigned)idx*8, wsrc + 2*idx, true);
        }
        cpa_commit();
    };

    u64 acc[OCB][9];
#pragma unroll
    for (int o = 0; o < OCB; o++)
#pragma unroll
        for (int d = 0; d < 9; d++) acc[o][d] = 0ull;

    issue(0);

    int gstart = (tid >> 5) << 1;    // 0,2,4,6 — per-warp group rotation
    int cellbase = (ty*18 + tx)*28;  // floats

    for (int s = 0; s < CPAIRS; s++) {
        asm volatile("cp.async.wait_group 0;");   // group s landed
        __syncthreads();
        // Single barrier: publishes group s AND proves all warps finished
        // step s-1 (which read buf (s+1)&1), so that buf is free to refill.
        if (s + 1 < CPAIRS) issue(s + 1);

        int cur = s & 1;
        const float* tb = tile[cur];
        const float* wsb = wsh[cur];
#pragma unroll
        for (int gi = 0; gi < 9; gi++) {
            int grp = gstart + gi; if (grp >= 9) grp -= 9;
            int k0 = grp / 3;
            int k1 = grp - 3*k0;

            const ulonglong2* xq =
                (const ulonglong2*)(tb + cellbase + (k0*18 + k1)*28);
            ulonglong2 x12 = xq[0], x34 = xq[1], x56 = xq[2], x78 = xq[3];
            u64 x9v = ((const u64*)xq)[8];
            u64 xs[9] = {x12.x, x12.y, x34.x, x34.y, x56.x, x56.y, x78.x, x78.y, x9v};

#pragma unroll
            for (int tt = 0; tt < OCB/3; tt++) {
                const ulonglong2* wq =
                    (const ulonglong2*)(wsb + grp*WGRP + tt*20);
                ulonglong2 wA = wq[0], wB = wq[1], wC = wq[2], wD = wq[3];
                u64 w8v = ((const u64*)wq)[8];
                u64 w_[9] = {wA.x, wA.y, wB.x, wB.y, wC.x, wC.y, wD.x, wD.y, w8v};

#pragma unroll
                for (int z = 1; z <= 9; z++) {
                    u64 xv = xs[z - 1];
#pragma unroll
                    for (int k2 = 0; k2 < 3; k2++) {
                        int d = z - k2;
                        if (d >= 0 && d <= 8) {
#pragma unroll
                            for (int o = 0; o < 3; o++)
                                fma2(acc[tt*3 + o][d], w_[k2*3 + o], xv);
                        }
                    }
                }
            }
        }
    }

    int h = h0 + ty, w = w0 + tx;
    int pix = h*WW + w;
#pragma unroll
    for (int o = 0; o < OCB; o++) {
        int oc = g*OCB + o;
        float s  = gam[oc] * rsqrtf(var[oc] + EPSBN);
        float bi = (bias[oc] - mu[oc]) * s + bet[oc];
#pragma unroll
        for (int d = 0; d < 9; d++) {
            float lo, hi;
            upk2(lo, hi, acc[o][d]);
            float y = (lo + hi)*s + bi;
            if (FIRST) {
                y = fmaxf(y, 0.f);
                g_h12[(((size_t)(b*9 + (oc >> 1))*HWD) + pix*9 + d)*2 + (oc & 1)] = y;
            } else {
                float xg = g_xg[b*MM + oc];
                y = 1.f / (1.f + expf(-(y + xg)));
                g_wei[(size_t)(b*MM + oc)*HWD + pix*9 + d] = y;
            }
        }
    }
}

// ---------------------------------------------------------------------------
// K6: conv_last GEMM, oc-split (grid.z=2), on-the-fly A from interleaved cv,
// software-prefetched LDG, 3 blocks/SM.
// ---------------------------------------------------------------------------
extern __shared__ float sfin[];
__global__ __launch_bounds__(256, 3) void k_final(
        const float* __restrict__ clw, const float* __restrict__ clb,
        float* __restrict__ out) {
    float* Ws   = sfin;               // [144][80], slot j -> oc = oc0+j
    float* weis = sfin + 144*80;      // [9][128]
    int b   = blockIdx.y;
    int p0  = blockIdx.x * 128;
    int oc0 = blockIdx.z * 76;
    int jmax = (blockIdx.z == 0) ? 76 : 74;
    int tid = threadIdx.x;

    for (int t = tid; t < 80*144; t += 256) {
        int k = t % 144, j = t / 144;       // k-coalesced LDG
        int oc = oc0 + j;
        Ws[k*80 + j] = (oc < OUTC) ? clw[oc*MCC + k] : 0.f;
    }
    for (int t = tid; t < 9*128; t += 256) {
        int m = t >> 7, p = t & 127;
        weis[t] = g_wei[(size_t)(b*MM + m)*HWD + p0 + p];
    }
    __syncthreads();

    int tx = tid & 31, ty = tid >> 5;
    u64 acc[5][4];
#pragma unroll
    for (int j = 0; j < 5; j++)
#pragma unroll
        for (int i = 0; i < 4; i++) acc[j][i] = 0ull;

    const float* cvb = g_cv2 + ((size_t)b*72*HWD + (size_t)(p0 + tx*4))*2;

    float4 L0 = *(const float4*)(cvb);
    float4 L1 = *(const float4*)(cvb + 4);

    for (int cp = 0; cp < 72; cp++) {
        float4 P0 = make_float4(0.f,0.f,0.f,0.f), P1 = P0;
        if (cp < 71) {
            const float* nxt = cvb + (size_t)(cp + 1)*HWD*2;
            P0 = *(const float4*)(nxt);
            P1 = *(const float4*)(nxt + 4);
        }
        float4 wp = *(const float4*)(weis + (cp >> 3)*128 + tx*4);
        u64 e0 = pk2(L0.x*wp.x, L0.x*wp.x), e1 = pk2(L0.z*wp.y, L0.z*wp.y);
        u64 e2 = pk2(L1.x*wp.z, L1.x*wp.z), e3 = pk2(L1.z*wp.w, L1.z*wp.w);
        const u64* wr0 = (const u64*)(Ws + (2*cp)*80) + ty*5;
#pragma unroll
        for (int j = 0; j < 5; j++) {
            u64 wv = wr0[j];
            fma2(acc[j][0], wv, e0); fma2(acc[j][1], wv, e1);
            fma2(acc[j][2], wv, e2); fma2(acc[j][3], wv, e3);
        }
        u64 o0 = pk2(L0.y*wp.x, L0.y*wp.x), o1 = pk2(L0.w*wp.y, L0.w*wp.y);
        u64 o2 = pk2(L1.y*wp.z, L1.y*wp.z), o3 = pk2(L1.w*wp.w, L1.w*wp.w);
        const u64* wr1 = (const u64*)(Ws + (2*cp + 1)*80) + ty*5;
#pragma unroll
        for (int j = 0; j < 5; j++) {
            u64 wv = wr1[j];
            fma2(acc[j][0], wv, o0); fma2(acc[j][1], wv, o1);
            fma2(acc[j][2], wv, o2); fma2(acc[j][3], wv, o3);
        }
        L0 = P0; L1 = P1;
    }

#pragma unroll
    for (int j = 0; j < 5; j++) {
        int j0 = ty*10 + 2*j;
        float lo[4], hi[4];
#pragma unroll
        for (int i = 0; i < 4; i++) upk2(lo[i], hi[i], acc[j][i]);
        if (j0 < jmax) {
            int oc = oc0 + j0;
            float bv = clb[oc];
            float4 r = make_float4(lo[0]+bv, lo[1]+bv, lo[2]+bv, lo[3]+bv);
            *(float4*)(out + (size_t)(b*OUTC + oc)*HWD + p0 + tx*4) = r;
        }
        if (j0 + 1 < jmax) {
            int oc = oc0 + j0 + 1;
            float bv = clb[oc];
            float4 r = make_float4(hi[0]+bv, hi[1]+bv, hi[2]+bv, hi[3]+bv);
            *(float4*)(out + (size_t)(b*OUTC + oc)*HWD + p0 + tx*4) = r;
        }
    }
}

// ---------------------------------------------------------------------------
extern "C" void kernel_launch(void* const* d_in, const int* in_sizes, int n_in,
                              void* d_out, int out_size) {
    const float* x      = (const float*)d_in[0];
    const float* la_w1  = (const float*)d_in[1];
    const float* la_b1  = (const float*)d_in[2];
    const float* la_g1  = (const float*)d_in[3];
    const float* la_be1 = (const float*)d_in[4];
    const float* la_m1  = (const float*)d_in[5];
    const float* la_v1  = (const float*)d_in[6];
    const float* la_w2  = (const float*)d_in[7];
    const float* la_b2  = (const float*)d_in[8];
    const float* la_g2  = (const float*)d_in[9];
    const float* la_be2 = (const float*)d_in[10];
    const float* la_m2  = (const float*)d_in[11];
    const float* la_v2  = (const float*)d_in[12];
    const float* ga_w1  = (const float*)d_in[13];
    const float* ga_b1  = (const float*)d_in[14];
    const float* ga_g1  = (const float*)d_in[15];
    const float* ga_be1 = (const float*)d_in[16];
    const float* ga_m1  = (const float*)d_in[17];
    const float* ga_v1  = (const float*)d_in[18];
    const float* ga_w2  = (const float*)d_in[19];
    const float* ga_b2  = (const float*)d_in[20];
    const float* ga_g2  = (const float*)d_in[21];
    const float* ga_be2 = (const float*)d_in[22];
    const float* ga_m2  = (const float*)d_in[23];
    const float* ga_v2  = (const float*)d_in[24];
    const float* cl_w   = (const float*)d_in[25];
    const float* cl_b   = (const float*)d_in[26];
    float* out = (float*)d_out;

    // Launch order: conv1 at index 3 (profiler captures idx 3).
    k_packw<<<(HIDN*MCC*27 + 255)/256, 256>>>(la_w1, la_w2);              // 0
    unsigned ncell = BB*72*HW;
    k_build_cv<<<(ncell + 255)/256, 256>>>(x);                             // 1
    k_reduce<<<BB*MCC, 256>>>(x);                                          // 2

    // conv1: 6 oc per block (NOCG=3) -> cv tile traffic 3x instead of 6x
    dim3 g1(WW/16, HH/8, BB*3);
    k_conv<72, 3, 6, true><<<g1, 128>>>(la_g1, la_be1, la_m1, la_v1, la_b1);  // 3

    k_global<<<1, 64>>>(ga_w1, ga_b1, ga_g1, ga_be1, ga_m1, ga_v1,
                        ga_w2, ga_b2, ga_g2, ga_be2, ga_m2, ga_v2);        // 4

    dim3 g2(WW/16, HH/8, BB*3);
    k_conv<9, 3, 3, false><<<g2, 128>>>(la_g2, la_be2, la_m2, la_v2, la_b2);   // 5

    const int smem_fin = (144*80 + 9*128) * 4;   // 50688
    cudaFuncSetAttribute(k_final, cudaFuncAttributeMaxDynamicSharedMemorySize, smem_fin);
    dim3 gf(HWD/128, BB, 2);
    k_final<<<gf, 256, smem_fin>>>(cl_w, cl_b, out);                       // 6
}